// round 9
// baseline (speedup 1.0000x reference)
#include <cuda_runtime.h>
#include <cuda_bf16.h>
#include <math.h>
#include <cstdint>

#define NN 50000
#define NE 800000

// ---------------- scratch (static device memory; no allocs) ----------------
__device__ int   g_cnt[NN];
__device__ int   g_row[NN + 1];
__device__ int   g_csr[NE];
__device__ float g_he[NN];
__device__ float g_h0[NN * 64];
__device__ float g_h1[NN * 64];

// ---------------- helpers ----------------
__device__ __forceinline__ uint32_t smem_u32(const void* p) {
    uint32_t a;
    asm("{ .reg .u64 t; cvta.to.shared.u64 t, %1; cvt.u32.u64 %0, t; }" : "=r"(a) : "l"(p));
    return a;
}
__device__ __forceinline__ uint32_t pack_hi(float x, float y) {
    uint32_t a = (uint32_t)__bfloat16_as_ushort(__float2bfloat16(x));
    uint32_t b = (uint32_t)__bfloat16_as_ushort(__float2bfloat16(y));
    return a | (b << 16);
}
__device__ __forceinline__ uint32_t pack_lo(float x, float y) {
    float xr = x - __bfloat162float(__float2bfloat16(x));
    float yr = y - __bfloat162float(__float2bfloat16(y));
    uint32_t a = (uint32_t)__bfloat16_as_ushort(__float2bfloat16(xr));
    uint32_t b = (uint32_t)__bfloat16_as_ushort(__float2bfloat16(yr));
    return a | (b << 16);
}
// swizzled byte offset inside a [rows][128] bf16 tile with 256B rows:
// 16B chunk index kb = k>>3 is XORed with (row&7) -> conflict-free ldmatrix.
__device__ __forceinline__ int tsw(int row, int k) {
    int kb = k >> 3;
    return row * 256 + (((kb ^ (row & 7)) & 15) << 4) + (k & 7) * 2;
}

#define LDMX4(r0, r1, r2, r3, a) \
    asm volatile("ldmatrix.sync.aligned.m8n8.x4.shared.b16 {%0,%1,%2,%3}, [%4];" \
        : "=r"(r0), "=r"(r1), "=r"(r2), "=r"(r3) : "r"(a))
#define MMA16816(c0, c1, c2, c3, a0, a1, a2, a3, b0, b1) \
    asm volatile("mma.sync.aligned.m16n8k16.row.col.f32.bf16.bf16.f32 " \
        "{%0,%1,%2,%3}, {%4,%5,%6,%7}, {%8,%9}, {%0,%1,%2,%3};" \
        : "+f"(c0), "+f"(c1), "+f"(c2), "+f"(c3) \
        : "r"(a0), "r"(a1), "r"(a2), "r"(a3), "r"(b0), "r"(b1))

// ---------------- CSR build ----------------
__global__ void k_zero() {
    int i = blockIdx.x * blockDim.x + threadIdx.x;
    if (i < NN) { g_cnt[i] = 0; g_he[i] = 0.0f; }
}
__global__ void k_hist(const int* __restrict__ dst, const float* __restrict__ ef) {
    int e = blockIdx.x * blockDim.x + threadIdx.x;
    if (e < NE) {
        int d = dst[e];
        atomicAdd(&g_cnt[d], 1);
        atomicAdd(&g_he[d], ef[e]);
    }
}
__global__ void k_scan() {
    const int CH = 49;
    __shared__ int sums[1024];
    int t = threadIdx.x;
    int start = t * CH, end = min(start + CH, NN);
    int s = 0;
    for (int i = start; i < end; ++i) s += g_cnt[i];
    sums[t] = s;
    __syncthreads();
    #pragma unroll
    for (int off = 1; off < 1024; off <<= 1) {
        int mine = sums[t];
        int v = (t >= off) ? sums[t - off] : 0;
        __syncthreads();
        sums[t] = mine + v;
        __syncthreads();
    }
    int run = (t == 0) ? 0 : sums[t - 1];
    for (int i = start; i < end; ++i) {
        int c = g_cnt[i];
        g_row[i] = run;
        g_cnt[i] = run;
        run += c;
    }
    if (t == 1023) g_row[NN] = run;
}
__global__ void k_fill(const int* __restrict__ src, const int* __restrict__ dst) {
    int e = blockIdx.x * blockDim.x + threadIdx.x;
    if (e < NE) {
        int d = dst[e];
        int p = atomicAdd(&g_cnt[d], 1);
        g_csr[p] = src[e];
    }
}

// ---------------- smem layout (bytes) ----------------
#define OFF_BIAS 0
#define OFF_WCOL 256
#define OFF_SIDX 512
#define OFF_AHI  1536
#define OFF_ALO  (OFF_AHI + 16384)
#define OFF_BHI  (OFF_ALO + 16384)
#define OFF_BLO  (OFF_BHI + 16384)
#define SMEM_TOT (OFF_BLO + 16384)

// ---------------- fused agg + concat + mma.sync GEMM + bias + act ----------------
// Block = 64 nodes (M=64), 256 threads (8 warps: 4 m-tiles x 2 n-tiles).
// GEMM via 3-pass split-bf16: AhiBhi + AhiBlo + AloBhi.  ACT: 1 relu, 2 sigmoid
template <int ACT>
__global__ void __launch_bounds__(256, 3) k_fused(
    const float* __restrict__ h,
    const float* __restrict__ W,      // [64][129]
    const float* __restrict__ bias,   // [64]
    float* __restrict__ out) {
    extern __shared__ char smem[];
    uint32_t sb = smem_u32(smem);
    float* s_bias = (float*)(smem + OFF_BIAS);
    float* s_wcol = (float*)(smem + OFF_WCOL);
    int*   sidx   = (int*)(smem + OFF_SIDX);

    int tid  = threadIdx.x;
    int wid  = tid >> 5;
    int lane = tid & 31;
    int m0   = blockIdx.x * 64;

    if (tid < 64) {
        s_bias[tid] = bias[tid];
        s_wcol[tid] = W[tid * 129 + 128];
    }

    // stage W -> Bhi/Blo [64n][128k] swizzled
    #pragma unroll
    for (int t = 0; t < 16; ++t) {
        int u = tid + t * 256;          // 4096 k-pairs
        int n = u >> 6;
        int k = (u & 63) * 2;
        float w0 = W[n * 129 + k];
        float w1 = W[n * 129 + k + 1];
        int o = tsw(n, k);
        *(uint32_t*)(smem + OFF_BHI + o) = pack_hi(w0, w1);
        *(uint32_t*)(smem + OFF_BLO + o) = pack_lo(w0, w1);
    }

    // stage h half of A (cols 0..63) -> Ahi/Alo
    #pragma unroll
    for (int t = 0; t < 8; ++t) {
        int u = tid + t * 256;          // 2048 (m, k-pair)
        int m = u >> 5;
        int k = (u & 31) * 2;
        int gm = m0 + m;
        float2 v = make_float2(0.f, 0.f);
        if (gm < NN) v = *reinterpret_cast<const float2*>(h + gm * 64 + k);
        int o = tsw(m, k);
        *(uint32_t*)(smem + OFF_AHI + o) = pack_hi(v.x, v.y);
        *(uint32_t*)(smem + OFF_ALO + o) = pack_lo(v.x, v.y);
    }

    // neighbor aggregation: warp w handles nodes w+8i; lane owns feats 2l,2l+1
    #pragma unroll
    for (int i = 0; i < 8; ++i) {
        int mloc = wid + 8 * i;
        int gm   = m0 + mloc;
        float ax = 0.0f, ay = 0.0f;
        if (gm < NN) {
            int s = g_row[gm], e = g_row[gm + 1];
            int base = wid * 32;
            for (int c = s; c < e; c += 32) {
                int n = e - c; if (n > 32) n = 32;
                sidx[base + lane] = (c + lane < e) ? g_csr[c + lane] : 0;
                __syncwarp();
                for (int t = 0; t < n; t += 4) {
                    int u0 = sidx[base + t + 0];
                    int u1 = sidx[base + t + 1];
                    int u2 = sidx[base + t + 2];
                    int u3 = sidx[base + t + 3];
                    float2 v0 = *reinterpret_cast<const float2*>(h + (u0 << 6) + (lane << 1));
                    float2 v1 = *reinterpret_cast<const float2*>(h + (u1 << 6) + (lane << 1));
                    float2 v2 = *reinterpret_cast<const float2*>(h + (u2 << 6) + (lane << 1));
                    float2 v3 = *reinterpret_cast<const float2*>(h + (u3 << 6) + (lane << 1));
                    float w1 = (t + 1 < n) ? 1.0f : 0.0f;
                    float w2 = (t + 2 < n) ? 1.0f : 0.0f;
                    float w3 = (t + 3 < n) ? 1.0f : 0.0f;
                    ax += v0.x;               ay += v0.y;
                    ax = fmaf(w1, v1.x, ax);  ay = fmaf(w1, v1.y, ay);
                    ax = fmaf(w2, v2.x, ax);  ay = fmaf(w2, v2.y, ay);
                    ax = fmaf(w3, v3.x, ax);  ay = fmaf(w3, v3.y, ay);
                }
                __syncwarp();
            }
        }
        int o = tsw(mloc, 64 + 2 * lane);
        *(uint32_t*)(smem + OFF_AHI + o) = pack_hi(ax, ay);
        *(uint32_t*)(smem + OFF_ALO + o) = pack_lo(ax, ay);
    }
    __syncthreads();

    // GEMM: warp wm=wid>>1 (m-tile of 16 rows), wn=wid&1 (n-tile of 32 cols)
    int wm = wid >> 1;
    int wn = wid & 1;
    float c[4][4];
    #pragma unroll
    for (int t = 0; t < 4; ++t)
        #pragma unroll
        for (int j = 0; j < 4; ++j) c[t][j] = 0.0f;

    // precomputed lane pieces
    int ar  = lane & 15;                 // A row within tile
    int ac  = lane >> 4;                 // A k-chunk (0/1)
    int bro = ((lane >> 4) & 1) * 8 + (lane & 7);   // B n-row offset within 16-row group
    int bkc = (lane >> 3) & 1;           // B k-chunk (0/1)

    #pragma unroll
    for (int pass = 0; pass < 3; ++pass) {
        uint32_t abase = sb + ((pass == 2) ? OFF_ALO : OFF_AHI);
        uint32_t bbase = sb + ((pass == 1) ? OFF_BLO : OFF_BHI);
        #pragma unroll
        for (int ks = 0; ks < 8; ++ks) {
            uint32_t a0, a1, a2, a3;
            {
                int row = wm * 16 + ar;
                uint32_t addr = abase + tsw(row, ks * 16 + ac * 8);
                LDMX4(a0, a1, a2, a3, addr);
            }
            // B [n][k] row-major IS col-major KxN -> NON-trans ldmatrix.
            // matrices: b0 = n0-7/k0-7, b1 = n0-7/k8-15, b2 = n8-15/k0-7, b3 = n8-15/k8-15
            uint32_t b[8];
            #pragma unroll
            for (int t2 = 0; t2 < 2; ++t2) {
                int n = wn * 32 + t2 * 16 + bro;
                uint32_t addr = bbase + tsw(n, ks * 16 + bkc * 8);
                LDMX4(b[t2 * 4 + 0], b[t2 * 4 + 1], b[t2 * 4 + 2], b[t2 * 4 + 3], addr);
            }
            #pragma unroll
            for (int t = 0; t < 4; ++t) {
                int t2 = t >> 1;
                int pr = (t & 1) * 2;
                MMA16816(c[t][0], c[t][1], c[t][2], c[t][3],
                         a0, a1, a2, a3, b[t2 * 4 + pr], b[t2 * 4 + pr + 1]);
            }
        }
    }

    // epilogue: rows g, g+8 of this m-tile; cols per n8-tile
    int g    = lane >> 2;
    int m_lo = m0 + wm * 16 + g;
    int m_hi = m_lo + 8;
    float he0 = (m_lo < NN) ? g_he[m_lo] : 0.0f;
    float he1 = (m_hi < NN) ? g_he[m_hi] : 0.0f;
    #pragma unroll
    for (int t = 0; t < 4; ++t) {
        int n = wn * 32 + t * 8 + (lane & 3) * 2;
        float b0 = s_bias[n],     b1 = s_bias[n + 1];
        float w0 = s_wcol[n],     w1 = s_wcol[n + 1];
        if (m_lo < NN) {
            float v0 = c[t][0] + b0 + he0 * w0;
            float v1 = c[t][1] + b1 + he0 * w1;
            if (ACT == 1) { v0 = fmaxf(v0, 0.f); v1 = fmaxf(v1, 0.f); }
            else if (ACT == 2) {
                v0 = 1.0f / (1.0f + expf(-v0));
                v1 = 1.0f / (1.0f + expf(-v1));
            }
            *reinterpret_cast<float2*>(out + m_lo * 64 + n) = make_float2(v0, v1);
        }
        if (m_hi < NN) {
            float v2 = c[t][2] + b0 + he1 * w0;
            float v3 = c[t][3] + b1 + he1 * w1;
            if (ACT == 1) { v2 = fmaxf(v2, 0.f); v3 = fmaxf(v3, 0.f); }
            else if (ACT == 2) {
                v2 = 1.0f / (1.0f + expf(-v2));
                v3 = 1.0f / (1.0f + expf(-v3));
            }
            *reinterpret_cast<float2*>(out + m_hi * 64 + n) = make_float2(v2, v3);
        }
    }
}

// ---------------- final layer fused: agg + 2-output GEMM (fp32 scalar) ----------------
#define AS_STRIDE 132
__global__ void __launch_bounds__(256) k_final(
    const float* __restrict__ h,
    const float* __restrict__ W2,   // [2][129]
    const float* __restrict__ b2,
    float* __restrict__ out) {
    __shared__ float As[64 * AS_STRIDE];
    __shared__ int   sidx[8 * 32];

    int tid  = threadIdx.x;
    int w    = tid >> 5;
    int lane = tid & 31;
    int m0   = blockIdx.x * 64;

    #pragma unroll
    for (int t = 0; t < 4; ++t) {
        int u  = tid + t * 256;
        int m  = u >> 4;
        int kq = u & 15;
        int gm = m0 + m;
        float4 v = make_float4(0.f, 0.f, 0.f, 0.f);
        if (gm < NN) v = *reinterpret_cast<const float4*>(h + gm * 64 + kq * 4);
        *reinterpret_cast<float4*>(&As[m * AS_STRIDE + kq * 4]) = v;
    }

    #pragma unroll
    for (int i = 0; i < 8; ++i) {
        int mloc = w + 8 * i;
        int gm   = m0 + mloc;
        float ax = 0.0f, ay = 0.0f;
        if (gm < NN) {
            int s = g_row[gm], e = g_row[gm + 1];
            int base = w * 32;
            for (int c = s; c < e; c += 32) {
                int n = e - c; if (n > 32) n = 32;
                sidx[base + lane] = (c + lane < e) ? g_csr[c + lane] : 0;
                __syncwarp();
                for (int t = 0; t < n; t += 4) {
                    int u0 = sidx[base + t + 0];
                    int u1 = sidx[base + t + 1];
                    int u2 = sidx[base + t + 2];
                    int u3 = sidx[base + t + 3];
                    float2 v0 = *reinterpret_cast<const float2*>(h + (u0 << 6) + (lane << 1));
                    float2 v1 = *reinterpret_cast<const float2*>(h + (u1 << 6) + (lane << 1));
                    float2 v2 = *reinterpret_cast<const float2*>(h + (u2 << 6) + (lane << 1));
                    float2 v3 = *reinterpret_cast<const float2*>(h + (u3 << 6) + (lane << 1));
                    float w1 = (t + 1 < n) ? 1.0f : 0.0f;
                    float w2 = (t + 2 < n) ? 1.0f : 0.0f;
                    float w3 = (t + 3 < n) ? 1.0f : 0.0f;
                    ax += v0.x;               ay += v0.y;
                    ax = fmaf(w1, v1.x, ax);  ay = fmaf(w1, v1.y, ay);
                    ax = fmaf(w2, v2.x, ax);  ay = fmaf(w2, v2.y, ay);
                    ax = fmaf(w3, v3.x, ax);  ay = fmaf(w3, v3.y, ay);
                }
                __syncwarp();
            }
        }
        *reinterpret_cast<float2*>(&As[mloc * AS_STRIDE + 64 + (lane << 1)])
            = make_float2(ax, ay);
    }
    __syncthreads();

    if (tid < 128) {
        int mloc = tid >> 1;
        int cls  = tid & 1;
        int m    = m0 + mloc;
        if (m < NN) {
            const float* Wr = W2 + cls * 129;
            float a = __ldg(&b2[cls]) + g_he[m] * __ldg(&Wr[128]);
            #pragma unroll
            for (int kq = 0; kq < 32; ++kq) {
                float4 x = *reinterpret_cast<const float4*>(&As[mloc * AS_STRIDE + kq * 4]);
                a += x.x * __ldg(&Wr[kq * 4 + 0]);
                a += x.y * __ldg(&Wr[kq * 4 + 1]);
                a += x.z * __ldg(&Wr[kq * 4 + 2]);
                a += x.w * __ldg(&Wr[kq * 4 + 3]);
            }
            out[m * 2 + cls] = a;
        }
    }
}

// ---------------- driver ----------------
extern "C" void kernel_launch(void* const* d_in, const int* in_sizes, int n_in,
                              void* d_out, int out_size) {
    const float* node_feat = (const float*)d_in[0];
    const float* edge_feat = (const float*)d_in[1];
    const int*   src       = (const int*)d_in[2];
    const int*   dst       = (const int*)d_in[3];
    const float* W1        = (const float*)d_in[4];
    const float* b1        = (const float*)d_in[5];
    const float* Wmid      = (const float*)d_in[6];
    const float* bmid      = (const float*)d_in[7];
    const float* W2        = (const float*)d_in[8];
    const float* b2        = (const float*)d_in[9];
    float* out = (float*)d_out;

    float *h0, *h1;
    cudaGetSymbolAddress((void**)&h0, g_h0);
    cudaGetSymbolAddress((void**)&h1, g_h1);

    static bool attr_done = false;
    if (!attr_done) {
        cudaFuncSetAttribute(k_fused<1>, cudaFuncAttributeMaxDynamicSharedMemorySize, SMEM_TOT);
        cudaFuncSetAttribute(k_fused<2>, cudaFuncAttributeMaxDynamicSharedMemorySize, SMEM_TOT);
        attr_done = true;
    }

    const int EB = (NE + 255) / 256;
    const int GB = (NN + 63) / 64;

    k_zero<<<(NN + 255) / 256, 256>>>();
    k_hist<<<EB, 256>>>(dst, edge_feat);
    k_scan<<<1, 1024>>>();
    k_fill<<<EB, 256>>>(src, dst);

    // layer 1: 64->64, relu
    k_fused<1><<<GB, 256, SMEM_TOT>>>(node_feat, W1, b1, h0);

    // 5 mid layers: relu x4, sigmoid on last
    float* cur = h0;
    float* nxt = h1;
    for (int i = 0; i < 5; ++i) {
        const float* Wi = Wmid + i * 64 * 129;
        const float* bi = bmid + i * 64;
        if (i < 4) k_fused<1><<<GB, 256, SMEM_TOT>>>(cur, Wi, bi, nxt);
        else       k_fused<2><<<GB, 256, SMEM_TOT>>>(cur, Wi, bi, nxt);
        float* t = cur; cur = nxt; nxt = t;
    }

    // final layer: agg + 64->2 GEMM fused (fp32)
    k_final<<<GB, 256>>>(cur, W2, b2, out);
}

// round 10
// speedup vs baseline: 1.4993x; 1.4993x over previous
#include <cuda_runtime.h>
#include <cuda_bf16.h>
#include <math.h>
#include <cstdint>

#define NN 50000
#define NE 800000

// ---------------- scratch (static device memory; no allocs) ----------------
__device__ int   g_cnt[NN];
__device__ int   g_row[NN + 1];
__device__ int   g_csr[NE];
__device__ float g_he[NN];
__device__ float g_h0[NN * 64];
__device__ float g_h1[NN * 64];

// ---------------- helpers ----------------
__device__ __forceinline__ uint32_t smem_u32(const void* p) {
    uint32_t a;
    asm("{ .reg .u64 t; cvta.to.shared.u64 t, %1; cvt.u32.u64 %0, t; }" : "=r"(a) : "l"(p));
    return a;
}
__device__ __forceinline__ uint32_t pack_hi(float x, float y) {
    uint32_t a = (uint32_t)__bfloat16_as_ushort(__float2bfloat16(x));
    uint32_t b = (uint32_t)__bfloat16_as_ushort(__float2bfloat16(y));
    return a | (b << 16);
}
__device__ __forceinline__ uint32_t pack_lo(float x, float y) {
    float xr = x - __bfloat162float(__float2bfloat16(x));
    float yr = y - __bfloat162float(__float2bfloat16(y));
    uint32_t a = (uint32_t)__bfloat16_as_ushort(__float2bfloat16(xr));
    uint32_t b = (uint32_t)__bfloat16_as_ushort(__float2bfloat16(yr));
    return a | (b << 16);
}
// swizzled byte offset inside a [rows][128] bf16 tile with 256B rows:
// 16B chunk index kb = k>>3 is XORed with (row&7) -> conflict-free ldmatrix.
__device__ __forceinline__ int tsw(int row, int k) {
    int kb = k >> 3;
    return row * 256 + (((kb ^ (row & 7)) & 15) << 4) + (k & 7) * 2;
}

#define LDMX4(r0, r1, r2, r3, a) \
    asm volatile("ldmatrix.sync.aligned.m8n8.x4.shared.b16 {%0,%1,%2,%3}, [%4];" \
        : "=r"(r0), "=r"(r1), "=r"(r2), "=r"(r3) : "r"(a))
#define MMA16816(c0, c1, c2, c3, a0, a1, a2, a3, b0, b1) \
    asm volatile("mma.sync.aligned.m16n8k16.row.col.f32.bf16.bf16.f32 " \
        "{%0,%1,%2,%3}, {%4,%5,%6,%7}, {%8,%9}, {%0,%1,%2,%3};" \
        : "+f"(c0), "+f"(c1), "+f"(c2), "+f"(c3) \
        : "r"(a0), "r"(a1), "r"(a2), "r"(a3), "r"(b0), "r"(b1))

// ---------------- CSR build ----------------
__global__ void k_zero() {
    int i = blockIdx.x * blockDim.x + threadIdx.x;
    if (i < NN) { g_cnt[i] = 0; g_he[i] = 0.0f; }
}
__global__ void k_hist(const int* __restrict__ dst, const float* __restrict__ ef) {
    int e = blockIdx.x * blockDim.x + threadIdx.x;
    if (e < NE) {
        int d = dst[e];
        atomicAdd(&g_cnt[d], 1);
        atomicAdd(&g_he[d], ef[e]);
    }
}
__global__ void k_scan() {
    const int CH = 49;
    __shared__ int sums[1024];
    int t = threadIdx.x;
    int start = t * CH, end = min(start + CH, NN);
    int s = 0;
    for (int i = start; i < end; ++i) s += g_cnt[i];
    sums[t] = s;
    __syncthreads();
    #pragma unroll
    for (int off = 1; off < 1024; off <<= 1) {
        int mine = sums[t];
        int v = (t >= off) ? sums[t - off] : 0;
        __syncthreads();
        sums[t] = mine + v;
        __syncthreads();
    }
    int run = (t == 0) ? 0 : sums[t - 1];
    for (int i = start; i < end; ++i) {
        int c = g_cnt[i];
        g_row[i] = run;
        g_cnt[i] = run;
        run += c;
    }
    if (t == 1023) g_row[NN] = run;
}
__global__ void k_fill(const int* __restrict__ src, const int* __restrict__ dst) {
    int e = blockIdx.x * blockDim.x + threadIdx.x;
    if (e < NE) {
        int d = dst[e];
        int p = atomicAdd(&g_cnt[d], 1);
        g_csr[p] = src[e];
    }
}

// ---------------- smem layout (bytes) ----------------
#define OFF_BIAS 0
#define OFF_WCOL 256
#define OFF_SIDX 512
#define OFF_AHI  1536
#define OFF_ALO  (OFF_AHI + 16384)
#define OFF_BHI  (OFF_ALO + 16384)
#define OFF_BLO  (OFF_BHI + 16384)
#define SMEM_TOT (OFF_BLO + 16384)

// ---------------- fused agg + concat + mma.sync GEMM + bias + act ----------------
// Block = 64 nodes (M=64), 256 threads (8 warps: 4 m-tiles x 2 n-tiles).
// GEMM via 3-pass split-bf16: AhiBhi + AhiBlo + AloBhi, all 3 passes fused
// into one k-loop (fragments loaded once per k-step). ACT: 1 relu, 2 sigmoid
template <int ACT>
__global__ void __launch_bounds__(256, 2) k_fused(
    const float* __restrict__ h,
    const float* __restrict__ W,      // [64][129]
    const float* __restrict__ bias,   // [64]
    float* __restrict__ out) {
    extern __shared__ char smem[];
    uint32_t sb = smem_u32(smem);
    float* s_bias = (float*)(smem + OFF_BIAS);
    float* s_wcol = (float*)(smem + OFF_WCOL);
    int*   sidx   = (int*)(smem + OFF_SIDX);

    int tid  = threadIdx.x;
    int wid  = tid >> 5;
    int lane = tid & 31;
    int m0   = blockIdx.x * 64;

    if (tid < 64) {
        s_bias[tid] = bias[tid];
        s_wcol[tid] = W[tid * 129 + 128];
    }

    // stage W -> Bhi/Blo [64n][128k] swizzled
    #pragma unroll
    for (int t = 0; t < 16; ++t) {
        int u = tid + t * 256;          // 4096 k-pairs
        int n = u >> 6;
        int k = (u & 63) * 2;
        float w0 = W[n * 129 + k];
        float w1 = W[n * 129 + k + 1];
        int o = tsw(n, k);
        *(uint32_t*)(smem + OFF_BHI + o) = pack_hi(w0, w1);
        *(uint32_t*)(smem + OFF_BLO + o) = pack_lo(w0, w1);
    }

    // stage h half of A (cols 0..63) -> Ahi/Alo
    #pragma unroll
    for (int t = 0; t < 8; ++t) {
        int u = tid + t * 256;          // 2048 (m, k-pair)
        int m = u >> 5;
        int k = (u & 31) * 2;
        int gm = m0 + m;
        float2 v = make_float2(0.f, 0.f);
        if (gm < NN) v = *reinterpret_cast<const float2*>(h + gm * 64 + k);
        int o = tsw(m, k);
        *(uint32_t*)(smem + OFF_AHI + o) = pack_hi(v.x, v.y);
        *(uint32_t*)(smem + OFF_ALO + o) = pack_lo(v.x, v.y);
    }

    // neighbor aggregation: warp w handles nodes w+8i; lane owns feats 2l,2l+1
    #pragma unroll
    for (int i = 0; i < 8; ++i) {
        int mloc = wid + 8 * i;
        int gm   = m0 + mloc;
        float ax = 0.0f, ay = 0.0f;
        if (gm < NN) {
            int s = g_row[gm], e = g_row[gm + 1];
            int base = wid * 32;
            for (int c = s; c < e; c += 32) {
                int n = e - c; if (n > 32) n = 32;
                sidx[base + lane] = (c + lane < e) ? g_csr[c + lane] : 0;
                __syncwarp();
                for (int t = 0; t < n; t += 4) {
                    int u0 = sidx[base + t + 0];
                    int u1 = sidx[base + t + 1];
                    int u2 = sidx[base + t + 2];
                    int u3 = sidx[base + t + 3];
                    float2 v0 = *reinterpret_cast<const float2*>(h + (u0 << 6) + (lane << 1));
                    float2 v1 = *reinterpret_cast<const float2*>(h + (u1 << 6) + (lane << 1));
                    float2 v2 = *reinterpret_cast<const float2*>(h + (u2 << 6) + (lane << 1));
                    float2 v3 = *reinterpret_cast<const float2*>(h + (u3 << 6) + (lane << 1));
                    float w1 = (t + 1 < n) ? 1.0f : 0.0f;
                    float w2 = (t + 2 < n) ? 1.0f : 0.0f;
                    float w3 = (t + 3 < n) ? 1.0f : 0.0f;
                    ax += v0.x;               ay += v0.y;
                    ax = fmaf(w1, v1.x, ax);  ay = fmaf(w1, v1.y, ay);
                    ax = fmaf(w2, v2.x, ax);  ay = fmaf(w2, v2.y, ay);
                    ax = fmaf(w3, v3.x, ax);  ay = fmaf(w3, v3.y, ay);
                }
                __syncwarp();
            }
        }
        int o = tsw(mloc, 64 + 2 * lane);
        *(uint32_t*)(smem + OFF_AHI + o) = pack_hi(ax, ay);
        *(uint32_t*)(smem + OFF_ALO + o) = pack_lo(ax, ay);
    }
    __syncthreads();

    // GEMM: warp wm=wid>>1 (m-tile of 16 rows), wn=wid&1 (n-tile of 32 cols)
    int wm = wid >> 1;
    int wn = wid & 1;
    float c[4][4];
    #pragma unroll
    for (int t = 0; t < 4; ++t)
        #pragma unroll
        for (int j = 0; j < 4; ++j) c[t][j] = 0.0f;

    // precomputed lane pieces
    int ar  = lane & 15;                 // A row within tile
    int ac  = lane >> 4;                 // A k-chunk (0/1)
    int bro = ((lane >> 4) & 1) * 8 + (lane & 7);   // B n-row offset within 16-row group
    int bkc = (lane >> 3) & 1;           // B k-chunk (0/1)

    #pragma unroll
    for (int ks = 0; ks < 8; ++ks) {
        int row = wm * 16 + ar;
        uint32_t a_addr = tsw(row, ks * 16 + ac * 8);
        uint32_t ahi0, ahi1, ahi2, ahi3, alo0, alo1, alo2, alo3;
        LDMX4(ahi0, ahi1, ahi2, ahi3, sb + OFF_AHI + a_addr);
        LDMX4(alo0, alo1, alo2, alo3, sb + OFF_ALO + a_addr);

        // B [n][k] row-major IS col-major KxN -> NON-trans ldmatrix.
        uint32_t bhi[8], blo[8];
        #pragma unroll
        for (int t2 = 0; t2 < 2; ++t2) {
            int n = wn * 32 + t2 * 16 + bro;
            uint32_t b_addr = tsw(n, ks * 16 + bkc * 8);
            LDMX4(bhi[t2 * 4 + 0], bhi[t2 * 4 + 1], bhi[t2 * 4 + 2], bhi[t2 * 4 + 3],
                  sb + OFF_BHI + b_addr);
            LDMX4(blo[t2 * 4 + 0], blo[t2 * 4 + 1], blo[t2 * 4 + 2], blo[t2 * 4 + 3],
                  sb + OFF_BLO + b_addr);
        }
        #pragma unroll
        for (int t = 0; t < 4; ++t) {
            int t2 = t >> 1;
            int pr = (t & 1) * 2;
            MMA16816(c[t][0], c[t][1], c[t][2], c[t][3],
                     ahi0, ahi1, ahi2, ahi3, bhi[t2 * 4 + pr], bhi[t2 * 4 + pr + 1]);
            MMA16816(c[t][0], c[t][1], c[t][2], c[t][3],
                     ahi0, ahi1, ahi2, ahi3, blo[t2 * 4 + pr], blo[t2 * 4 + pr + 1]);
            MMA16816(c[t][0], c[t][1], c[t][2], c[t][3],
                     alo0, alo1, alo2, alo3, bhi[t2 * 4 + pr], bhi[t2 * 4 + pr + 1]);
        }
    }

    // epilogue: rows g, g+8 of this m-tile; cols per n8-tile
    int g    = lane >> 2;
    int m_lo = m0 + wm * 16 + g;
    int m_hi = m_lo + 8;
    float he0 = (m_lo < NN) ? g_he[m_lo] : 0.0f;
    float he1 = (m_hi < NN) ? g_he[m_hi] : 0.0f;
    #pragma unroll
    for (int t = 0; t < 4; ++t) {
        int n = wn * 32 + t * 8 + (lane & 3) * 2;
        float b0 = s_bias[n],     b1 = s_bias[n + 1];
        float w0 = s_wcol[n],     w1 = s_wcol[n + 1];
        if (m_lo < NN) {
            float v0 = c[t][0] + b0 + he0 * w0;
            float v1 = c[t][1] + b1 + he0 * w1;
            if (ACT == 1) { v0 = fmaxf(v0, 0.f); v1 = fmaxf(v1, 0.f); }
            else if (ACT == 2) {
                v0 = 1.0f / (1.0f + expf(-v0));
                v1 = 1.0f / (1.0f + expf(-v1));
            }
            *reinterpret_cast<float2*>(out + m_lo * 64 + n) = make_float2(v0, v1);
        }
        if (m_hi < NN) {
            float v2 = c[t][2] + b0 + he1 * w0;
            float v3 = c[t][3] + b1 + he1 * w1;
            if (ACT == 1) { v2 = fmaxf(v2, 0.f); v3 = fmaxf(v3, 0.f); }
            else if (ACT == 2) {
                v2 = 1.0f / (1.0f + expf(-v2));
                v3 = 1.0f / (1.0f + expf(-v3));
            }
            *reinterpret_cast<float2*>(out + m_hi * 64 + n) = make_float2(v2, v3);
        }
    }
}

// ---------------- final layer fused: agg + 2-output GEMM (fp32 scalar) ----------------
#define AS_STRIDE 132
__global__ void __launch_bounds__(256) k_final(
    const float* __restrict__ h,
    const float* __restrict__ W2,   // [2][129]
    const float* __restrict__ b2,
    float* __restrict__ out) {
    __shared__ float As[64 * AS_STRIDE];
    __shared__ int   sidx[8 * 32];

    int tid  = threadIdx.x;
    int w    = tid >> 5;
    int lane = tid & 31;
    int m0   = blockIdx.x * 64;

    #pragma unroll
    for (int t = 0; t < 4; ++t) {
        int u  = tid + t * 256;
        int m  = u >> 4;
        int kq = u & 15;
        int gm = m0 + m;
        float4 v = make_float4(0.f, 0.f, 0.f, 0.f);
        if (gm < NN) v = *reinterpret_cast<const float4*>(h + gm * 64 + kq * 4);
        *reinterpret_cast<float4*>(&As[m * AS_STRIDE + kq * 4]) = v;
    }

    #pragma unroll
    for (int i = 0; i < 8; ++i) {
        int mloc = w + 8 * i;
        int gm   = m0 + mloc;
        float ax = 0.0f, ay = 0.0f;
        if (gm < NN) {
            int s = g_row[gm], e = g_row[gm + 1];
            int base = w * 32;
            for (int c = s; c < e; c += 32) {
                int n = e - c; if (n > 32) n = 32;
                sidx[base + lane] = (c + lane < e) ? g_csr[c + lane] : 0;
                __syncwarp();
                for (int t = 0; t < n; t += 4) {
                    int u0 = sidx[base + t + 0];
                    int u1 = sidx[base + t + 1];
                    int u2 = sidx[base + t + 2];
                    int u3 = sidx[base + t + 3];
                    float2 v0 = *reinterpret_cast<const float2*>(h + (u0 << 6) + (lane << 1));
                    float2 v1 = *reinterpret_cast<const float2*>(h + (u1 << 6) + (lane << 1));
                    float2 v2 = *reinterpret_cast<const float2*>(h + (u2 << 6) + (lane << 1));
                    float2 v3 = *reinterpret_cast<const float2*>(h + (u3 << 6) + (lane << 1));
                    float w1 = (t + 1 < n) ? 1.0f : 0.0f;
                    float w2 = (t + 2 < n) ? 1.0f : 0.0f;
                    float w3 = (t + 3 < n) ? 1.0f : 0.0f;
                    ax += v0.x;               ay += v0.y;
                    ax = fmaf(w1, v1.x, ax);  ay = fmaf(w1, v1.y, ay);
                    ax = fmaf(w2, v2.x, ax);  ay = fmaf(w2, v2.y, ay);
                    ax = fmaf(w3, v3.x, ax);  ay = fmaf(w3, v3.y, ay);
                }
                __syncwarp();
            }
        }
        *reinterpret_cast<float2*>(&As[mloc * AS_STRIDE + 64 + (lane << 1)])
            = make_float2(ax, ay);
    }
    __syncthreads();

    if (tid < 128) {
        int mloc = tid >> 1;
        int cls  = tid & 1;
        int m    = m0 + mloc;
        if (m < NN) {
            const float* Wr = W2 + cls * 129;
            float a = __ldg(&b2[cls]) + g_he[m] * __ldg(&Wr[128]);
            #pragma unroll
            for (int kq = 0; kq < 32; ++kq) {
                float4 x = *reinterpret_cast<const float4*>(&As[mloc * AS_STRIDE + kq * 4]);
                a += x.x * __ldg(&Wr[kq * 4 + 0]);
                a += x.y * __ldg(&Wr[kq * 4 + 1]);
                a += x.z * __ldg(&Wr[kq * 4 + 2]);
                a += x.w * __ldg(&Wr[kq * 4 + 3]);
            }
            out[m * 2 + cls] = a;
        }
    }
}

// ---------------- driver ----------------
extern "C" void kernel_launch(void* const* d_in, const int* in_sizes, int n_in,
                              void* d_out, int out_size) {
    const float* node_feat = (const float*)d_in[0];
    const float* edge_feat = (const float*)d_in[1];
    const int*   src       = (const int*)d_in[2];
    const int*   dst       = (const int*)d_in[3];
    const float* W1        = (const float*)d_in[4];
    const float* b1        = (const float*)d_in[5];
    const float* Wmid      = (const float*)d_in[6];
    const float* bmid      = (const float*)d_in[7];
    const float* W2        = (const float*)d_in[8];
    const float* b2        = (const float*)d_in[9];
    float* out = (float*)d_out;

    float *h0, *h1;
    cudaGetSymbolAddress((void**)&h0, g_h0);
    cudaGetSymbolAddress((void**)&h1, g_h1);

    static bool attr_done = false;
    if (!attr_done) {
        cudaFuncSetAttribute(k_fused<1>, cudaFuncAttributeMaxDynamicSharedMemorySize, SMEM_TOT);
        cudaFuncSetAttribute(k_fused<2>, cudaFuncAttributeMaxDynamicSharedMemorySize, SMEM_TOT);
        attr_done = true;
    }

    const int EB = (NE + 255) / 256;
    const int GB = (NN + 63) / 64;

    k_zero<<<(NN + 255) / 256, 256>>>();
    k_hist<<<EB, 256>>>(dst, edge_feat);
    k_scan<<<1, 1024>>>();
    k_fill<<<EB, 256>>>(src, dst);

    // layer 1: 64->64, relu
    k_fused<1><<<GB, 256, SMEM_TOT>>>(node_feat, W1, b1, h0);

    // 5 mid layers: relu x4, sigmoid on last
    float* cur = h0;
    float* nxt = h1;
    for (int i = 0; i < 5; ++i) {
        const float* Wi = Wmid + i * 64 * 129;
        const float* bi = bmid + i * 64;
        if (i < 4) k_fused<1><<<GB, 256, SMEM_TOT>>>(cur, Wi, bi, nxt);
        else       k_fused<2><<<GB, 256, SMEM_TOT>>>(cur, Wi, bi, nxt);
        float* t = cur; cur = nxt; nxt = t;
    }

    // final layer: agg + 64->2 GEMM fused (fp32)
    k_final<<<GB, 256>>>(cur, W2, b2, out);
}

// round 12
// speedup vs baseline: 1.7344x; 1.1568x over previous
#include <cuda_runtime.h>
#include <cuda_bf16.h>
#include <math.h>
#include <cstdint>

#define NN 50000
#define NE 800000

// ---------------- scratch (static device memory; no allocs) ----------------
__device__ int      g_cnt[NN];
__device__ int      g_row[NN + 1];
__device__ int      g_csr[NE];
__device__ float    g_he[NN];
__device__ float    g_h0[NN * 64];
__device__ float    g_h1[NN * 64];
__device__ uint32_t g_whi[6 * 4096];   // per-layer 16KB swizzled bf16-hi W tile
__device__ uint32_t g_wlo[6 * 4096];   // per-layer 16KB swizzled bf16-lo W tile
__device__ float    g_wcolp[6 * 64];   // per-layer he-coefficient column

// ---------------- helpers ----------------
__device__ __forceinline__ uint32_t smem_u32(const void* p) {
    uint32_t a;
    asm("{ .reg .u64 t; cvta.to.shared.u64 t, %1; cvt.u32.u64 %0, t; }" : "=r"(a) : "l"(p));
    return a;
}
__device__ __forceinline__ uint32_t pack_hi(float x, float y) {
    uint32_t a = (uint32_t)__bfloat16_as_ushort(__float2bfloat16(x));
    uint32_t b = (uint32_t)__bfloat16_as_ushort(__float2bfloat16(y));
    return a | (b << 16);
}
__device__ __forceinline__ uint32_t pack_lo(float x, float y) {
    float xr = x - __bfloat162float(__float2bfloat16(x));
    float yr = y - __bfloat162float(__float2bfloat16(y));
    uint32_t a = (uint32_t)__bfloat16_as_ushort(__float2bfloat16(xr));
    uint32_t b = (uint32_t)__bfloat16_as_ushort(__float2bfloat16(yr));
    return a | (b << 16);
}
// swizzled byte offset inside a [rows][128] bf16 tile with 256B rows:
// 16B chunk index kb = k>>3 is XORed with (row&7) -> conflict-free ldmatrix.
__device__ __forceinline__ int tsw(int row, int k) {
    int kb = k >> 3;
    return row * 256 + (((kb ^ (row & 7)) & 15) << 4) + (k & 7) * 2;
}

#define LDMX4(r0, r1, r2, r3, a) \
    asm volatile("ldmatrix.sync.aligned.m8n8.x4.shared.b16 {%0,%1,%2,%3}, [%4];" \
        : "=r"(r0), "=r"(r1), "=r"(r2), "=r"(r3) : "r"(a))
#define MMA16816(c0, c1, c2, c3, a0, a1, a2, a3, b0, b1) \
    asm volatile("mma.sync.aligned.m16n8k16.row.col.f32.bf16.bf16.f32 " \
        "{%0,%1,%2,%3}, {%4,%5,%6,%7}, {%8,%9}, {%0,%1,%2,%3};" \
        : "+f"(c0), "+f"(c1), "+f"(c2), "+f"(c3) \
        : "r"(a0), "r"(a1), "r"(a2), "r"(a3), "r"(b0), "r"(b1))

// ---------------- CSR build ----------------
__global__ void k_zero() {
    int i = blockIdx.x * blockDim.x + threadIdx.x;
    if (i < NN) { g_cnt[i] = 0; g_he[i] = 0.0f; }
}
__global__ void k_hist(const int* __restrict__ dst, const float* __restrict__ ef) {
    int e = blockIdx.x * blockDim.x + threadIdx.x;
    if (e < NE) {
        int d = dst[e];
        atomicAdd(&g_cnt[d], 1);
        atomicAdd(&g_he[d], ef[e]);
    }
}
__global__ void k_scan() {
    const int CH = 49;
    __shared__ int sums[1024];
    int t = threadIdx.x;
    int start = t * CH, end = min(start + CH, NN);
    int s = 0;
    for (int i = start; i < end; ++i) s += g_cnt[i];
    sums[t] = s;
    __syncthreads();
    #pragma unroll
    for (int off = 1; off < 1024; off <<= 1) {
        int mine = sums[t];
        int v = (t >= off) ? sums[t - off] : 0;
        __syncthreads();
        sums[t] = mine + v;
        __syncthreads();
    }
    int run = (t == 0) ? 0 : sums[t - 1];
    for (int i = start; i < end; ++i) {
        int c = g_cnt[i];
        g_row[i] = run;
        g_cnt[i] = run;
        run += c;
    }
    if (t == 1023) g_row[NN] = run;
}
__global__ void k_fill(const int* __restrict__ src, const int* __restrict__ dst) {
    int e = blockIdx.x * blockDim.x + threadIdx.x;
    if (e < NE) {
        int d = dst[e];
        int p = atomicAdd(&g_cnt[d], 1);
        g_csr[p] = src[e];
    }
}

// ---------------- weight prepack: 6 layers -> swizzled hi/lo tiles ----------------
__global__ void k_prepw(const float* __restrict__ W1, const float* __restrict__ Wmid) {
    int u = blockIdx.x * blockDim.x + threadIdx.x;
    if (u >= 6 * 4096) return;
    int L = u >> 12;
    int v = u & 4095;
    int n = v >> 6;
    int k = (v & 63) * 2;
    const float* W = (L == 0) ? W1 : (Wmid + (L - 1) * 64 * 129);
    float w0 = W[n * 129 + k];
    float w1 = W[n * 129 + k + 1];
    int o = tsw(n, k);
    g_whi[L * 4096 + (o >> 2)] = pack_hi(w0, w1);
    g_wlo[L * 4096 + (o >> 2)] = pack_lo(w0, w1);
    if (v < 64) g_wcolp[L * 64 + v] = W[v * 129 + 128];
}

// ---------------- smem layout (bytes) ----------------
#define OFF_BIAS 0
#define OFF_WCOL 256
#define OFF_SIDX 512
#define OFF_AHI  1536
#define OFF_ALO  (OFF_AHI + 16384)
#define OFF_BHI  (OFF_ALO + 16384)
#define OFF_BLO  (OFF_BHI + 16384)
#define SMEM_TOT (OFF_BLO + 16384)

// ---------------- fused agg + concat + mma.sync GEMM + bias + act ----------------
// Block = 64 nodes, 256 threads (8 warps: 4 m-tiles x 2 n-tiles).
// W comes prepacked (hi/lo swizzled tiles) -> staging is a raw uint4 copy.
// GEMM: 3-pass split-bf16 fused in one k-loop. ACT: 1 relu, 2 sigmoid
template <int ACT>
__global__ void __launch_bounds__(256, 2) k_fused(
    const float* __restrict__ h,
    const uint32_t* __restrict__ whi,   // [4096] swizzled tile
    const uint32_t* __restrict__ wlo,   // [4096]
    const float* __restrict__ wcol,     // [64]
    const float* __restrict__ bias,     // [64]
    float* __restrict__ out) {
    extern __shared__ char smem[];
    uint32_t sb = smem_u32(smem);
    float* s_bias = (float*)(smem + OFF_BIAS);
    float* s_wcol = (float*)(smem + OFF_WCOL);
    int*   sidx   = (int*)(smem + OFF_SIDX);

    int tid  = threadIdx.x;
    int wid  = tid >> 5;
    int lane = tid & 31;
    int m0   = blockIdx.x * 64;

    if (tid < 64) {
        s_bias[tid] = bias[tid];
        s_wcol[tid] = wcol[tid];
    }

    // stage W: raw copy of prepacked swizzled tiles (16KB hi + 16KB lo)
    {
        const uint4* shi = (const uint4*)whi;
        const uint4* slo = (const uint4*)wlo;
        uint4* dhi = (uint4*)(smem + OFF_BHI);
        uint4* dlo = (uint4*)(smem + OFF_BLO);
        #pragma unroll
        for (int t = 0; t < 4; ++t) {
            int u = tid + t * 256;
            dhi[u] = shi[u];
            dlo[u] = slo[u];
        }
    }

    // stage h half of A (cols 0..63) -> Ahi/Alo, float4 loads
    #pragma unroll
    for (int t = 0; t < 4; ++t) {
        int u  = tid + t * 256;         // 1024 (m, k-quad)
        int m  = u >> 4;
        int kq = u & 15;
        int k  = kq * 4;
        int gm = m0 + m;
        float4 v = make_float4(0.f, 0.f, 0.f, 0.f);
        if (gm < NN) v = *reinterpret_cast<const float4*>(h + gm * 64 + k);
        int o = tsw(m, k);
        uint2 phi = make_uint2(pack_hi(v.x, v.y), pack_hi(v.z, v.w));
        uint2 plo = make_uint2(pack_lo(v.x, v.y), pack_lo(v.z, v.w));
        *(uint2*)(smem + OFF_AHI + o) = phi;
        *(uint2*)(smem + OFF_ALO + o) = plo;
    }

    // neighbor aggregation: warp w handles nodes w+8i; lane owns feats 2l,2l+1.
    // 8 edges per batch (sidx padded with node 0 -> all loads unconditional, MLP=8)
    #pragma unroll
    for (int i = 0; i < 8; ++i) {
        int mloc = wid + 8 * i;
        int gm   = m0 + mloc;
        float ax = 0.0f, ay = 0.0f;
        if (gm < NN) {
            int s = g_row[gm], e = g_row[gm + 1];
            int base = wid * 32;
            for (int c = s; c < e; c += 32) {
                int n = e - c; if (n > 32) n = 32;
                sidx[base + lane] = (c + lane < e) ? g_csr[c + lane] : 0;
                __syncwarp();
                for (int t = 0; t < n; t += 8) {
                    float2 v[8];
                    #pragma unroll
                    for (int q = 0; q < 8; ++q) {
                        int u = sidx[base + t + q];
                        v[q] = *reinterpret_cast<const float2*>(h + (u << 6) + (lane << 1));
                    }
                    ax += v[0].x;  ay += v[0].y;
                    #pragma unroll
                    for (int q = 1; q < 8; ++q) {
                        float wq = (t + q < n) ? 1.0f : 0.0f;
                        ax = fmaf(wq, v[q].x, ax);
                        ay = fmaf(wq, v[q].y, ay);
                    }
                }
                __syncwarp();
            }
        }
        int o = tsw(mloc, 64 + 2 * lane);
        *(uint32_t*)(smem + OFF_AHI + o) = pack_hi(ax, ay);
        *(uint32_t*)(smem + OFF_ALO + o) = pack_lo(ax, ay);
    }
    __syncthreads();

    // GEMM: warp wm=wid>>1 (m-tile of 16 rows), wn=wid&1 (n-tile of 32 cols)
    int wm = wid >> 1;
    int wn = wid & 1;
    float c[4][4];
    #pragma unroll
    for (int t = 0; t < 4; ++t)
        #pragma unroll
        for (int j = 0; j < 4; ++j) c[t][j] = 0.0f;

    int ar  = lane & 15;                 // A row within tile
    int ac  = lane >> 4;                 // A k-chunk (0/1)
    int bro = ((lane >> 4) & 1) * 8 + (lane & 7);   // B n-row offset
    int bkc = (lane >> 3) & 1;           // B k-chunk (0/1)

    #pragma unroll
    for (int ks = 0; ks < 8; ++ks) {
        int row = wm * 16 + ar;
        uint32_t a_addr = tsw(row, ks * 16 + ac * 8);
        uint32_t ahi0, ahi1, ahi2, ahi3, alo0, alo1, alo2, alo3;
        LDMX4(ahi0, ahi1, ahi2, ahi3, sb + OFF_AHI + a_addr);
        LDMX4(alo0, alo1, alo2, alo3, sb + OFF_ALO + a_addr);

        // B [n][k] row-major IS col-major KxN -> NON-trans ldmatrix.
        uint32_t bhi[8], blo[8];
        #pragma unroll
        for (int t2 = 0; t2 < 2; ++t2) {
            int n = wn * 32 + t2 * 16 + bro;
            uint32_t b_addr = tsw(n, ks * 16 + bkc * 8);
            LDMX4(bhi[t2 * 4 + 0], bhi[t2 * 4 + 1], bhi[t2 * 4 + 2], bhi[t2 * 4 + 3],
                  sb + OFF_BHI + b_addr);
            LDMX4(blo[t2 * 4 + 0], blo[t2 * 4 + 1], blo[t2 * 4 + 2], blo[t2 * 4 + 3],
                  sb + OFF_BLO + b_addr);
        }
        #pragma unroll
        for (int t = 0; t < 4; ++t) {
            int t2 = t >> 1;
            int pr = (t & 1) * 2;
            MMA16816(c[t][0], c[t][1], c[t][2], c[t][3],
                     ahi0, ahi1, ahi2, ahi3, bhi[t2 * 4 + pr], bhi[t2 * 4 + pr + 1]);
            MMA16816(c[t][0], c[t][1], c[t][2], c[t][3],
                     ahi0, ahi1, ahi2, ahi3, blo[t2 * 4 + pr], blo[t2 * 4 + pr + 1]);
            MMA16816(c[t][0], c[t][1], c[t][2], c[t][3],
                     alo0, alo1, alo2, alo3, bhi[t2 * 4 + pr], bhi[t2 * 4 + pr + 1]);
        }
    }

    // epilogue: rows g, g+8 of this m-tile; cols per n8-tile
    int g    = lane >> 2;
    int m_lo = m0 + wm * 16 + g;
    int m_hi = m_lo + 8;
    float he0 = (m_lo < NN) ? g_he[m_lo] : 0.0f;
    float he1 = (m_hi < NN) ? g_he[m_hi] : 0.0f;
    #pragma unroll
    for (int t = 0; t < 4; ++t) {
        int n = wn * 32 + t * 8 + (lane & 3) * 2;
        float b0 = s_bias[n],     b1 = s_bias[n + 1];
        float w0 = s_wcol[n],     w1 = s_wcol[n + 1];
        if (m_lo < NN) {
            float v0 = c[t][0] + b0 + he0 * w0;
            float v1 = c[t][1] + b1 + he0 * w1;
            if (ACT == 1) { v0 = fmaxf(v0, 0.f); v1 = fmaxf(v1, 0.f); }
            else if (ACT == 2) {
                v0 = 1.0f / (1.0f + expf(-v0));
                v1 = 1.0f / (1.0f + expf(-v1));
            }
            *reinterpret_cast<float2*>(out + m_lo * 64 + n) = make_float2(v0, v1);
        }
        if (m_hi < NN) {
            float v2 = c[t][2] + b0 + he1 * w0;
            float v3 = c[t][3] + b1 + he1 * w1;
            if (ACT == 1) { v2 = fmaxf(v2, 0.f); v3 = fmaxf(v3, 0.f); }
            else if (ACT == 2) {
                v2 = 1.0f / (1.0f + expf(-v2));
                v3 = 1.0f / (1.0f + expf(-v3));
            }
            *reinterpret_cast<float2*>(out + m_hi * 64 + n) = make_float2(v2, v3);
        }
    }
}

// ---------------- final layer fused: agg + 2-output GEMM (fp32 scalar) ----------------
#define AS_STRIDE 132
__global__ void __launch_bounds__(256) k_final(
    const float* __restrict__ h,
    const float* __restrict__ W2,   // [2][129]
    const float* __restrict__ b2,
    float* __restrict__ out) {
    __shared__ float As[64 * AS_STRIDE];
    __shared__ int   sidx[8 * 32];

    int tid  = threadIdx.x;
    int w    = tid >> 5;
    int lane = tid & 31;
    int m0   = blockIdx.x * 64;

    #pragma unroll
    for (int t = 0; t < 4; ++t) {
        int u  = tid + t * 256;
        int m  = u >> 4;
        int kq = u & 15;
        int gm = m0 + m;
        float4 v = make_float4(0.f, 0.f, 0.f, 0.f);
        if (gm < NN) v = *reinterpret_cast<const float4*>(h + gm * 64 + kq * 4);
        *reinterpret_cast<float4*>(&As[m * AS_STRIDE + kq * 4]) = v;
    }

    #pragma unroll
    for (int i = 0; i < 8; ++i) {
        int mloc = w + 8 * i;
        int gm   = m0 + mloc;
        float ax = 0.0f, ay = 0.0f;
        if (gm < NN) {
            int s = g_row[gm], e = g_row[gm + 1];
            int base = w * 32;
            for (int c = s; c < e; c += 32) {
                int n = e - c; if (n > 32) n = 32;
                sidx[base + lane] = (c + lane < e) ? g_csr[c + lane] : 0;
                __syncwarp();
                for (int t = 0; t < n; t += 8) {
                    float2 v[8];
                    #pragma unroll
                    for (int q = 0; q < 8; ++q) {
                        int u = sidx[base + t + q];
                        v[q] = *reinterpret_cast<const float2*>(h + (u << 6) + (lane << 1));
                    }
                    ax += v[0].x;  ay += v[0].y;
                    #pragma unroll
                    for (int q = 1; q < 8; ++q) {
                        float wq = (t + q < n) ? 1.0f : 0.0f;
                        ax = fmaf(wq, v[q].x, ax);
                        ay = fmaf(wq, v[q].y, ay);
                    }
                }
                __syncwarp();
            }
        }
        *reinterpret_cast<float2*>(&As[mloc * AS_STRIDE + 64 + (lane << 1)])
            = make_float2(ax, ay);
    }
    __syncthreads();

    if (tid < 128) {
        int mloc = tid >> 1;
        int cls  = tid & 1;
        int m    = m0 + mloc;
        if (m < NN) {
            const float* Wr = W2 + cls * 129;
            float a = __ldg(&b2[cls]) + g_he[m] * __ldg(&Wr[128]);
            #pragma unroll
            for (int kq = 0; kq < 32; ++kq) {
                float4 x = *reinterpret_cast<const float4*>(&As[mloc * AS_STRIDE + kq * 4]);
                a += x.x * __ldg(&Wr[kq * 4 + 0]);
                a += x.y * __ldg(&Wr[kq * 4 + 1]);
                a += x.z * __ldg(&Wr[kq * 4 + 2]);
                a += x.w * __ldg(&Wr[kq * 4 + 3]);
            }
            out[m * 2 + cls] = a;
        }
    }
}

// ---------------- driver ----------------
extern "C" void kernel_launch(void* const* d_in, const int* in_sizes, int n_in,
                              void* d_out, int out_size) {
    const float* node_feat = (const float*)d_in[0];
    const float* edge_feat = (const float*)d_in[1];
    const int*   src       = (const int*)d_in[2];
    const int*   dst       = (const int*)d_in[3];
    const float* W1        = (const float*)d_in[4];
    const float* b1        = (const float*)d_in[5];
    const float* Wmid      = (const float*)d_in[6];
    const float* bmid      = (const float*)d_in[7];
    const float* W2        = (const float*)d_in[8];
    const float* b2        = (const float*)d_in[9];
    float* out = (float*)d_out;

    float *h0, *h1, *wcolp;
    uint32_t *whi, *wlo;
    cudaGetSymbolAddress((void**)&h0, g_h0);
    cudaGetSymbolAddress((void**)&h1, g_h1);
    cudaGetSymbolAddress((void**)&whi, g_whi);
    cudaGetSymbolAddress((void**)&wlo, g_wlo);
    cudaGetSymbolAddress((void**)&wcolp, g_wcolp);

    static bool attr_done = false;
    if (!attr_done) {
        cudaFuncSetAttribute(k_fused<1>, cudaFuncAttributeMaxDynamicSharedMemorySize, SMEM_TOT);
        cudaFuncSetAttribute(k_fused<2>, cudaFuncAttributeMaxDynamicSharedMemorySize, SMEM_TOT);
        attr_done = true;
    }

    const int EB = (NE + 255) / 256;
    const int GB = (NN + 63) / 64;

    k_zero<<<(NN + 255) / 256, 256>>>();
    k_hist<<<EB, 256>>>(dst, edge_feat);
    k_prepw<<<96, 256>>>(W1, Wmid);
    k_scan<<<1, 1024>>>();
    k_fill<<<EB, 256>>>(src, dst);

    // layer 1: 64->64, relu
    k_fused<1><<<GB, 256, SMEM_TOT>>>(node_feat, whi, wlo, wcolp, b1, h0);

    // 5 mid layers: relu x4, sigmoid on last
    float* cur = h0;
    float* nxt = h1;
    for (int i = 0; i < 5; ++i) {
        const uint32_t* whiL = whi + (i + 1) * 4096;
        const uint32_t* wloL = wlo + (i + 1) * 4096;
        const float*    wcL  = wcolp + (i + 1) * 64;
        const float*    biL  = bmid + i * 64;
        if (i < 4) k_fused<1><<<GB, 256, SMEM_TOT>>>(cur, whiL, wloL, wcL, biL, nxt);
        else       k_fused<2><<<GB, 256, SMEM_TOT>>>(cur, whiL, wloL, wcL, biL, nxt);
        float* t = cur; cur = nxt; nxt = t;
    }

    // final layer: agg + 64->2 GEMM fused (fp32)
    k_final<<<GB, 256>>>(cur, W2, b2, out);
}

// round 13
// speedup vs baseline: 2.1254x; 1.2255x over previous
#include <cuda_runtime.h>
#include <cuda_bf16.h>
#include <math.h>
#include <cstdint>

#define NN 50000
#define NE 800000
#define SCAN_B 196              // ceil(50000/256)

// ---------------- scratch (static device memory; no allocs) ----------------
__device__ int      g_cnt[NN];
__device__ int      g_row[NN + 1];
__device__ int      g_csr[NE];
__device__ float    g_he[NN];
__device__ float    g_h0[NN * 64];
__device__ float    g_h1[NN * 64];
__device__ int      g_bsum[SCAN_B];
__device__ int      g_boff[SCAN_B];
__device__ uint32_t g_whi[6 * 4096];   // per-layer 16KB swizzled bf16-hi W tile
__device__ uint32_t g_wlo[6 * 4096];   // per-layer 16KB swizzled bf16-lo W tile
__device__ float    g_wcolp[6 * 64];   // per-layer he-coefficient column

// ---------------- helpers ----------------
__device__ __forceinline__ uint32_t smem_u32(const void* p) {
    uint32_t a;
    asm("{ .reg .u64 t; cvta.to.shared.u64 t, %1; cvt.u32.u64 %0, t; }" : "=r"(a) : "l"(p));
    return a;
}
__device__ __forceinline__ uint32_t pack_hi(float x, float y) {
    uint32_t a = (uint32_t)__bfloat16_as_ushort(__float2bfloat16(x));
    uint32_t b = (uint32_t)__bfloat16_as_ushort(__float2bfloat16(y));
    return a | (b << 16);
}
__device__ __forceinline__ uint32_t pack_lo(float x, float y) {
    float xr = x - __bfloat162float(__float2bfloat16(x));
    float yr = y - __bfloat162float(__float2bfloat16(y));
    uint32_t a = (uint32_t)__bfloat16_as_ushort(__float2bfloat16(xr));
    uint32_t b = (uint32_t)__bfloat16_as_ushort(__float2bfloat16(yr));
    return a | (b << 16);
}
// swizzled byte offset inside a [rows][128] bf16 tile with 256B rows:
// 16B chunk index kb = k>>3 is XORed with (row&7) -> conflict-free ldmatrix.
__device__ __forceinline__ int tsw(int row, int k) {
    int kb = k >> 3;
    return row * 256 + (((kb ^ (row & 7)) & 15) << 4) + (k & 7) * 2;
}

#define LDMX4(r0, r1, r2, r3, a) \
    asm volatile("ldmatrix.sync.aligned.m8n8.x4.shared.b16 {%0,%1,%2,%3}, [%4];" \
        : "=r"(r0), "=r"(r1), "=r"(r2), "=r"(r3) : "r"(a))
#define MMA16816(c0, c1, c2, c3, a0, a1, a2, a3, b0, b1) \
    asm volatile("mma.sync.aligned.m16n8k16.row.col.f32.bf16.bf16.f32 " \
        "{%0,%1,%2,%3}, {%4,%5,%6,%7}, {%8,%9}, {%0,%1,%2,%3};" \
        : "+f"(c0), "+f"(c1), "+f"(c2), "+f"(c3) \
        : "r"(a0), "r"(a1), "r"(a2), "r"(a3), "r"(b0), "r"(b1))

// ---------------- CSR build ----------------
__global__ void k_zero() {
    int i = blockIdx.x * blockDim.x + threadIdx.x;
    if (i < NN) { g_cnt[i] = 0; g_he[i] = 0.0f; }
}
__global__ void k_hist(const int* __restrict__ dst, const float* __restrict__ ef) {
    int e = blockIdx.x * blockDim.x + threadIdx.x;
    if (e < NE) {
        int d = dst[e];
        atomicAdd(&g_cnt[d], 1);
        atomicAdd(&g_he[d], ef[e]);
    }
}

// parallel scan, stage 1: per-block scan of 256 counts
__global__ void k_scan1() {
    __shared__ int s[256];
    int t = threadIdx.x;
    int i = blockIdx.x * 256 + t;
    int v = (i < NN) ? g_cnt[i] : 0;
    s[t] = v;
    __syncthreads();
    #pragma unroll
    for (int off = 1; off < 256; off <<= 1) {
        int mine = s[t];
        int add = (t >= off) ? s[t - off] : 0;
        __syncthreads();
        s[t] = mine + add;
        __syncthreads();
    }
    if (i < NN) g_row[i] = s[t] - v;          // block-local exclusive
    if (t == 255) g_bsum[blockIdx.x] = s[255]; // block total
}

// stage 2: exclusive scan of 196 block sums (single small block)
__global__ void k_scan2() {
    __shared__ int s[256];
    int t = threadIdx.x;
    int v = (t < SCAN_B) ? g_bsum[t] : 0;
    s[t] = v;
    __syncthreads();
    #pragma unroll
    for (int off = 1; off < 256; off <<= 1) {
        int mine = s[t];
        int add = (t >= off) ? s[t - off] : 0;
        __syncthreads();
        s[t] = mine + add;
        __syncthreads();
    }
    if (t < SCAN_B) g_boff[t] = s[t] - v;     // exclusive
}

// stage 3: add block offsets, prime cursor
__global__ void k_scan3() {
    int i = blockIdx.x * 256 + threadIdx.x;
    if (i < NN) {
        int r = g_row[i] + g_boff[blockIdx.x];
        g_row[i] = r;
        g_cnt[i] = r;
    }
    if (i == 0) g_row[NN] = NE;
}

__global__ void k_fill(const int* __restrict__ src, const int* __restrict__ dst) {
    int e = blockIdx.x * blockDim.x + threadIdx.x;
    if (e < NE) {
        int d = dst[e];
        int p = atomicAdd(&g_cnt[d], 1);
        g_csr[p] = src[e];
    }
}

// ---------------- weight prepack: 6 layers -> swizzled hi/lo tiles ----------------
__global__ void k_prepw(const float* __restrict__ W1, const float* __restrict__ Wmid) {
    int u = blockIdx.x * blockDim.x + threadIdx.x;
    if (u >= 6 * 4096) return;
    int L = u >> 12;
    int v = u & 4095;
    int n = v >> 6;
    int k = (v & 63) * 2;
    const float* W = (L == 0) ? W1 : (Wmid + (L - 1) * 64 * 129);
    float w0 = W[n * 129 + k];
    float w1 = W[n * 129 + k + 1];
    int o = tsw(n, k);
    g_whi[L * 4096 + (o >> 2)] = pack_hi(w0, w1);
    g_wlo[L * 4096 + (o >> 2)] = pack_lo(w0, w1);
    if (v < 64) g_wcolp[L * 64 + v] = W[v * 129 + 128];
}

// ---------------- smem layout (bytes) ----------------
#define OFF_BIAS 0
#define OFF_WCOL 256
#define OFF_SIDX 512
#define OFF_AHI  1536
#define OFF_ALO  (OFF_AHI + 16384)
#define OFF_BHI  (OFF_ALO + 16384)
#define OFF_BLO  (OFF_BHI + 16384)
#define SMEM_TOT (OFF_BLO + 16384)

// ---------------- fused agg + concat + mma.sync GEMM + bias + act ----------------
// Block = 64 nodes, 256 threads (8 warps: 4 m-tiles x 2 n-tiles).
// W comes prepacked (hi/lo swizzled tiles) -> staging is a raw uint4 copy.
// GEMM: 3-pass split-bf16 fused in one k-loop. ACT: 1 relu, 2 sigmoid
template <int ACT>
__global__ void __launch_bounds__(256, 2) k_fused(
    const float* __restrict__ h,
    const uint32_t* __restrict__ whi,   // [4096] swizzled tile
    const uint32_t* __restrict__ wlo,   // [4096]
    const float* __restrict__ wcol,     // [64]
    const float* __restrict__ bias,     // [64]
    float* __restrict__ out) {
    extern __shared__ char smem[];
    uint32_t sb = smem_u32(smem);
    float* s_bias = (float*)(smem + OFF_BIAS);
    float* s_wcol = (float*)(smem + OFF_WCOL);
    int*   sidx   = (int*)(smem + OFF_SIDX);

    int tid  = threadIdx.x;
    int wid  = tid >> 5;
    int lane = tid & 31;
    int m0   = blockIdx.x * 64;

    if (tid < 64) {
        s_bias[tid] = bias[tid];
        s_wcol[tid] = wcol[tid];
    }

    // stage W: raw copy of prepacked swizzled tiles (16KB hi + 16KB lo)
    {
        const uint4* shi = (const uint4*)whi;
        const uint4* slo = (const uint4*)wlo;
        uint4* dhi = (uint4*)(smem + OFF_BHI);
        uint4* dlo = (uint4*)(smem + OFF_BLO);
        #pragma unroll
        for (int t = 0; t < 4; ++t) {
            int u = tid + t * 256;
            dhi[u] = shi[u];
            dlo[u] = slo[u];
        }
    }

    // stage h half of A (cols 0..63) -> Ahi/Alo, float4 loads
    #pragma unroll
    for (int t = 0; t < 4; ++t) {
        int u  = tid + t * 256;         // 1024 (m, k-quad)
        int m  = u >> 4;
        int kq = u & 15;
        int k  = kq * 4;
        int gm = m0 + m;
        float4 v = make_float4(0.f, 0.f, 0.f, 0.f);
        if (gm < NN) v = *reinterpret_cast<const float4*>(h + gm * 64 + k);
        int o = tsw(m, k);
        uint2 phi = make_uint2(pack_hi(v.x, v.y), pack_hi(v.z, v.w));
        uint2 plo = make_uint2(pack_lo(v.x, v.y), pack_lo(v.z, v.w));
        *(uint2*)(smem + OFF_AHI + o) = phi;
        *(uint2*)(smem + OFF_ALO + o) = plo;
    }

    // neighbor aggregation: warp w handles nodes w+8i; lane owns feats 2l,2l+1.
    // 8 edges per batch (sidx padded with node 0 -> all loads unconditional, MLP=8)
    #pragma unroll
    for (int i = 0; i < 8; ++i) {
        int mloc = wid + 8 * i;
        int gm   = m0 + mloc;
        float ax = 0.0f, ay = 0.0f;
        if (gm < NN) {
            int s = g_row[gm], e = g_row[gm + 1];
            int base = wid * 32;
            for (int c = s; c < e; c += 32) {
                int n = e - c; if (n > 32) n = 32;
                sidx[base + lane] = (c + lane < e) ? g_csr[c + lane] : 0;
                __syncwarp();
                for (int t = 0; t < n; t += 8) {
                    float2 v[8];
                    #pragma unroll
                    for (int q = 0; q < 8; ++q) {
                        int u = sidx[base + t + q];
                        v[q] = *reinterpret_cast<const float2*>(h + (u << 6) + (lane << 1));
                    }
                    ax += v[0].x;  ay += v[0].y;
                    #pragma unroll
                    for (int q = 1; q < 8; ++q) {
                        float wq = (t + q < n) ? 1.0f : 0.0f;
                        ax = fmaf(wq, v[q].x, ax);
                        ay = fmaf(wq, v[q].y, ay);
                    }
                }
                __syncwarp();
            }
        }
        int o = tsw(mloc, 64 + 2 * lane);
        *(uint32_t*)(smem + OFF_AHI + o) = pack_hi(ax, ay);
        *(uint32_t*)(smem + OFF_ALO + o) = pack_lo(ax, ay);
    }
    __syncthreads();

    // GEMM: warp wm=wid>>1 (m-tile of 16 rows), wn=wid&1 (n-tile of 32 cols)
    int wm = wid >> 1;
    int wn = wid & 1;
    float c[4][4];
    #pragma unroll
    for (int t = 0; t < 4; ++t)
        #pragma unroll
        for (int j = 0; j < 4; ++j) c[t][j] = 0.0f;

    int ar  = lane & 15;                 // A row within tile
    int ac  = lane >> 4;                 // A k-chunk (0/1)
    int bro = ((lane >> 4) & 1) * 8 + (lane & 7);   // B n-row offset
    int bkc = (lane >> 3) & 1;           // B k-chunk (0/1)

    #pragma unroll
    for (int ks = 0; ks < 8; ++ks) {
        int row = wm * 16 + ar;
        uint32_t a_addr = tsw(row, ks * 16 + ac * 8);
        uint32_t ahi0, ahi1, ahi2, ahi3, alo0, alo1, alo2, alo3;
        LDMX4(ahi0, ahi1, ahi2, ahi3, sb + OFF_AHI + a_addr);
        LDMX4(alo0, alo1, alo2, alo3, sb + OFF_ALO + a_addr);

        // B [n][k] row-major IS col-major KxN -> NON-trans ldmatrix.
        uint32_t bhi[8], blo[8];
        #pragma unroll
        for (int t2 = 0; t2 < 2; ++t2) {
            int n = wn * 32 + t2 * 16 + bro;
            uint32_t b_addr = tsw(n, ks * 16 + bkc * 8);
            LDMX4(bhi[t2 * 4 + 0], bhi[t2 * 4 + 1], bhi[t2 * 4 + 2], bhi[t2 * 4 + 3],
                  sb + OFF_BHI + b_addr);
            LDMX4(blo[t2 * 4 + 0], blo[t2 * 4 + 1], blo[t2 * 4 + 2], blo[t2 * 4 + 3],
                  sb + OFF_BLO + b_addr);
        }
        #pragma unroll
        for (int t = 0; t < 4; ++t) {
            int t2 = t >> 1;
            int pr = (t & 1) * 2;
            MMA16816(c[t][0], c[t][1], c[t][2], c[t][3],
                     ahi0, ahi1, ahi2, ahi3, bhi[t2 * 4 + pr], bhi[t2 * 4 + pr + 1]);
            MMA16816(c[t][0], c[t][1], c[t][2], c[t][3],
                     ahi0, ahi1, ahi2, ahi3, blo[t2 * 4 + pr], blo[t2 * 4 + pr + 1]);
            MMA16816(c[t][0], c[t][1], c[t][2], c[t][3],
                     alo0, alo1, alo2, alo3, bhi[t2 * 4 + pr], bhi[t2 * 4 + pr + 1]);
        }
    }

    // epilogue: rows g, g+8 of this m-tile; cols per n8-tile
    int g    = lane >> 2;
    int m_lo = m0 + wm * 16 + g;
    int m_hi = m_lo + 8;
    float he0 = (m_lo < NN) ? g_he[m_lo] : 0.0f;
    float he1 = (m_hi < NN) ? g_he[m_hi] : 0.0f;
    #pragma unroll
    for (int t = 0; t < 4; ++t) {
        int n = wn * 32 + t * 8 + (lane & 3) * 2;
        float b0 = s_bias[n],     b1 = s_bias[n + 1];
        float w0 = s_wcol[n],     w1 = s_wcol[n + 1];
        if (m_lo < NN) {
            float v0 = c[t][0] + b0 + he0 * w0;
            float v1 = c[t][1] + b1 + he0 * w1;
            if (ACT == 1) { v0 = fmaxf(v0, 0.f); v1 = fmaxf(v1, 0.f); }
            else if (ACT == 2) {
                v0 = 1.0f / (1.0f + expf(-v0));
                v1 = 1.0f / (1.0f + expf(-v1));
            }
            *reinterpret_cast<float2*>(out + m_lo * 64 + n) = make_float2(v0, v1);
        }
        if (m_hi < NN) {
            float v2 = c[t][2] + b0 + he1 * w0;
            float v3 = c[t][3] + b1 + he1 * w1;
            if (ACT == 1) { v2 = fmaxf(v2, 0.f); v3 = fmaxf(v3, 0.f); }
            else if (ACT == 2) {
                v2 = 1.0f / (1.0f + expf(-v2));
                v3 = 1.0f / (1.0f + expf(-v3));
            }
            *reinterpret_cast<float2*>(out + m_hi * 64 + n) = make_float2(v2, v3);
        }
    }
}

// ---------------- final layer fused: agg + 2-output GEMM (fp32 scalar) ----------------
#define AS_STRIDE 132
__global__ void __launch_bounds__(256) k_final(
    const float* __restrict__ h,
    const float* __restrict__ W2,   // [2][129]
    const float* __restrict__ b2,
    float* __restrict__ out) {
    __shared__ float As[64 * AS_STRIDE];
    __shared__ int   sidx[8 * 32];

    int tid  = threadIdx.x;
    int w    = tid >> 5;
    int lane = tid & 31;
    int m0   = blockIdx.x * 64;

    #pragma unroll
    for (int t = 0; t < 4; ++t) {
        int u  = tid + t * 256;
        int m  = u >> 4;
        int kq = u & 15;
        int gm = m0 + m;
        float4 v = make_float4(0.f, 0.f, 0.f, 0.f);
        if (gm < NN) v = *reinterpret_cast<const float4*>(h + gm * 64 + kq * 4);
        *reinterpret_cast<float4*>(&As[m * AS_STRIDE + kq * 4]) = v;
    }

    #pragma unroll
    for (int i = 0; i < 8; ++i) {
        int mloc = w + 8 * i;
        int gm   = m0 + mloc;
        float ax = 0.0f, ay = 0.0f;
        if (gm < NN) {
            int s = g_row[gm], e = g_row[gm + 1];
            int base = w * 32;
            for (int c = s; c < e; c += 32) {
                int n = e - c; if (n > 32) n = 32;
                sidx[base + lane] = (c + lane < e) ? g_csr[c + lane] : 0;
                __syncwarp();
                for (int t = 0; t < n; t += 8) {
                    float2 v[8];
                    #pragma unroll
                    for (int q = 0; q < 8; ++q) {
                        int u = sidx[base + t + q];
                        v[q] = *reinterpret_cast<const float2*>(h + (u << 6) + (lane << 1));
                    }
                    ax += v[0].x;  ay += v[0].y;
                    #pragma unroll
                    for (int q = 1; q < 8; ++q) {
                        float wq = (t + q < n) ? 1.0f : 0.0f;
                        ax = fmaf(wq, v[q].x, ax);
                        ay = fmaf(wq, v[q].y, ay);
                    }
                }
                __syncwarp();
            }
        }
        *reinterpret_cast<float2*>(&As[mloc * AS_STRIDE + 64 + (lane << 1)])
            = make_float2(ax, ay);
    }
    __syncthreads();

    if (tid < 128) {
        int mloc = tid >> 1;
        int cls  = tid & 1;
        int m    = m0 + mloc;
        if (m < NN) {
            const float* Wr = W2 + cls * 129;
            float a = __ldg(&b2[cls]) + g_he[m] * __ldg(&Wr[128]);
            #pragma unroll
            for (int kq = 0; kq < 32; ++kq) {
                float4 x = *reinterpret_cast<const float4*>(&As[mloc * AS_STRIDE + kq * 4]);
                a += x.x * __ldg(&Wr[kq * 4 + 0]);
                a += x.y * __ldg(&Wr[kq * 4 + 1]);
                a += x.z * __ldg(&Wr[kq * 4 + 2]);
                a += x.w * __ldg(&Wr[kq * 4 + 3]);
            }
            out[m * 2 + cls] = a;
        }
    }
}

// ---------------- driver ----------------
extern "C" void kernel_launch(void* const* d_in, const int* in_sizes, int n_in,
                              void* d_out, int out_size) {
    const float* node_feat = (const float*)d_in[0];
    const float* edge_feat = (const float*)d_in[1];
    const int*   src       = (const int*)d_in[2];
    const int*   dst       = (const int*)d_in[3];
    const float* W1        = (const float*)d_in[4];
    const float* b1        = (const float*)d_in[5];
    const float* Wmid      = (const float*)d_in[6];
    const float* bmid      = (const float*)d_in[7];
    const float* W2        = (const float*)d_in[8];
    const float* b2        = (const float*)d_in[9];
    float* out = (float*)d_out;

    float *h0, *h1, *wcolp;
    uint32_t *whi, *wlo;
    cudaGetSymbolAddress((void**)&h0, g_h0);
    cudaGetSymbolAddress((void**)&h1, g_h1);
    cudaGetSymbolAddress((void**)&whi, g_whi);
    cudaGetSymbolAddress((void**)&wlo, g_wlo);
    cudaGetSymbolAddress((void**)&wcolp, g_wcolp);

    static bool attr_done = false;
    if (!attr_done) {
        cudaFuncSetAttribute(k_fused<1>, cudaFuncAttributeMaxDynamicSharedMemorySize, SMEM_TOT);
        cudaFuncSetAttribute(k_fused<2>, cudaFuncAttributeMaxDynamicSharedMemorySize, SMEM_TOT);
        attr_done = true;
    }

    const int EB = (NE + 255) / 256;
    const int GB = (NN + 63) / 64;

    k_zero<<<(NN + 255) / 256, 256>>>();
    k_hist<<<EB, 256>>>(dst, edge_feat);
    k_prepw<<<96, 256>>>(W1, Wmid);
    k_scan1<<<SCAN_B, 256>>>();
    k_scan2<<<1, 256>>>();
    k_scan3<<<SCAN_B, 256>>>();
    k_fill<<<EB, 256>>>(src, dst);

    // layer 1: 64->64, relu
    k_fused<1><<<GB, 256, SMEM_TOT>>>(node_feat, whi, wlo, wcolp, b1, h0);

    // 5 mid layers: relu x4, sigmoid on last
    float* cur = h0;
    float* nxt = h1;
    for (int i = 0; i < 5; ++i) {
        const uint32_t* whiL = whi + (i + 1) * 4096;
        const uint32_t* wloL = wlo + (i + 1) * 4096;
        const float*    wcL  = wcolp + (i + 1) * 64;
        const float*    biL  = bmid + i * 64;
        if (i < 4) k_fused<1><<<GB, 256, SMEM_TOT>>>(cur, whiL, wloL, wcL, biL, nxt);
        else       k_fused<2><<<GB, 256, SMEM_TOT>>>(cur, whiL, wloL, wcL, biL, nxt);
        float* t = cur; cur = nxt; nxt = t;
    }

    // final layer: agg + 64->2 GEMM fused (fp32)
    k_final<<<GB, 256>>>(cur, W2, b2, out);
}